// round 3
// baseline (speedup 1.0000x reference)
#include <cuda_runtime.h>
#include <math.h>

#define BATCH 64
#define EMB   512
#define HID   512
#define G3    1536         // 3*HID
#define VOCAB 10000
#define TSRC  128
#define TDEC  127          // trg[:, :-1]

// ---------------- scratch (device globals; no allocation allowed) ----------
__device__ float g_X [(size_t)BATCH * TSRC * EMB];   // embedded inputs
__device__ float g_GI[(size_t)BATCH * TSRC * G3];    // input projections (all t)
__device__ float g_Y [(size_t)BATCH * TSRC * HID];   // layer outputs
__device__ float g_H [4 * BATCH * HID];              // ping-pong hidden (2 layers x 2)
__device__ float g_PART[4 * BATCH * G3];             // split-K partials
__device__ unsigned int g_CNT[32];                   // per-j-tile arrival counters (monotonic)

// ---------------- init: zero out[t=0] slice + hidden buffers ----------------
__global__ void init_k(float* __restrict__ out)
{
    int i = blockIdx.x * blockDim.x + threadIdx.x;
    if (i < BATCH * VOCAB) {
        int b = i / VOCAB, v = i % VOCAB;
        out[((size_t)b * TSRC) * VOCAB + v] = 0.0f;
    }
    if (i < 4 * BATCH * HID) g_H[i] = 0.0f;
}

// ---------------- embedding gather (float4) ---------------------------------
__global__ void embed_k(const int* __restrict__ idx, const float* __restrict__ emb,
                        float* __restrict__ X, int T)
{
    int i = blockIdx.x * blockDim.x + threadIdx.x;
    int total = BATCH * T * (EMB / 4);
    if (i >= total) return;
    int e4 = i % (EMB / 4);
    int bt = i / (EMB / 4);
    int t  = bt % T;
    int b  = bt / T;
    int tok = idx[b * TSRC + t];               // idx rows have stride TSRC (128)
    reinterpret_cast<float4*>(X)[(size_t)bt * (EMB / 4) + e4] =
        reinterpret_cast<const float4*>(emb)[(size_t)tok * (EMB / 4) + e4];
}

// ---------------- generic tiled GEMM: C = A[M,K] @ W[N,K]^T + bias ----------
// mode 0: C[m*N + n]
// mode 1: FC scatter: m -> (b = m/TDEC, t = m%TDEC), C[((b*TSRC)+t+1)*VOCAB + n]
#define GTM 64
#define GTN 64
#define GTK 16
__global__ __launch_bounds__(256) void gemm_bias(
    const float* __restrict__ A, const float* __restrict__ W,
    const float* __restrict__ bias, float* __restrict__ C,
    int M, int N, int K, int mode)
{
    __shared__ float sA[GTK][GTM];
    __shared__ float sB[GTK][GTN];
    int m0 = blockIdx.x * GTM;
    int n0 = blockIdx.y * GTN;
    int tid = threadIdx.x;
    int tx = tid & 15;          // n micro index
    int ty = tid >> 4;          // m micro index
    int lm = tid >> 2;          // 0..63 (row for staging)
    int lk = (tid & 3) * 4;     // 0,4,8,12

    float acc[4][4];
#pragma unroll
    for (int i = 0; i < 4; i++)
#pragma unroll
        for (int j = 0; j < 4; j++) acc[i][j] = 0.0f;

    for (int k0 = 0; k0 < K; k0 += GTK) {
        float4 av = *reinterpret_cast<const float4*>(&A[(size_t)(m0 + lm) * K + k0 + lk]);
        float4 bv = make_float4(0.f, 0.f, 0.f, 0.f);
        int wn = n0 + lm;
        if (wn < N)
            bv = *reinterpret_cast<const float4*>(&W[(size_t)wn * K + k0 + lk]);
        __syncthreads();
        sA[lk + 0][lm] = av.x; sA[lk + 1][lm] = av.y;
        sA[lk + 2][lm] = av.z; sA[lk + 3][lm] = av.w;
        sB[lk + 0][lm] = bv.x; sB[lk + 1][lm] = bv.y;
        sB[lk + 2][lm] = bv.z; sB[lk + 3][lm] = bv.w;
        __syncthreads();
#pragma unroll
        for (int k = 0; k < GTK; k++) {
            float a[4], b[4];
            *reinterpret_cast<float4*>(a) = *reinterpret_cast<const float4*>(&sA[k][ty * 4]);
            *reinterpret_cast<float4*>(b) = *reinterpret_cast<const float4*>(&sB[k][tx * 4]);
#pragma unroll
            for (int i = 0; i < 4; i++)
#pragma unroll
                for (int j = 0; j < 4; j++)
                    acc[i][j] += a[i] * b[j];
        }
    }

#pragma unroll
    for (int i = 0; i < 4; i++) {
        int m = m0 + ty * 4 + i;
        size_t rowbase;
        if (mode == 0) {
            rowbase = (size_t)m * N;
        } else {
            int b = m / TDEC, t = m % TDEC;
            rowbase = ((size_t)b * TSRC + t + 1) * VOCAB;
        }
#pragma unroll
        for (int j = 0; j < 4; j++) {
            int n = n0 + tx * 4 + j;
            if (n < N) {
                C[rowbase + n] = acc[i][j] + bias[n];
            }
        }
    }
}

// ---------------- GRU recurrent step (split-K + fused gate combine) ---------
// Computes gh = h_in @ Whh^T, then (in the last-arriving block per j-tile):
// r = sig(gi_r+gh_r+bhh_r), z = sig(gi_z+gh_z+bhh_z), n = tanh(gi_n + r*(gh_n+bhh_n))
// h_new = (1-z)*n + z*h_prev.  GI already contains bih.
#define JT    16
#define SPLIT 4
#define KC    32
#define KPS   (HID / SPLIT)   // 128
__global__ __launch_bounds__(256) void gru_step(
    const float* __restrict__ h_in, const float* __restrict__ Whh,
    const float* __restrict__ bhh,  const float* __restrict__ GI,
    int t, int T,
    float* __restrict__ h_out, float* __restrict__ Yout)
{
    int tile = blockIdx.x & 31;      // j-tile: 32 tiles of 16 columns
    int s    = blockIdx.x >> 5;      // k-split 0..3
    int j0   = tile * JT;
    int k0   = s * KPS;
    int tid  = threadIdx.x;

    __shared__ float sW[3][JT][KC + 1];
    __shared__ float sH[BATCH][KC + 1];

    float accr[4] = {0.f, 0.f, 0.f, 0.f};
    float accz[4] = {0.f, 0.f, 0.f, 0.f};
    float accn[4] = {0.f, 0.f, 0.f, 0.f};
    int j  = tid & (JT - 1);
    int bg = tid / JT;
    int bb = bg * 4;

    for (int kc = 0; kc < KPS; kc += KC) {
        for (int i = tid; i < 3 * JT * KC; i += 256) {
            int g  = i / (JT * KC);
            int r  = i - g * (JT * KC);
            int jj = r / KC;
            int kk = r - jj * KC;
            sW[g][jj][kk] = Whh[(size_t)(g * HID + j0 + jj) * HID + k0 + kc + kk];
        }
        for (int i = tid; i < BATCH * KC; i += 256) {
            int bi = i / KC;
            int kk = i - bi * KC;
            sH[bi][kk] = h_in[bi * HID + k0 + kc + kk];
        }
        __syncthreads();
#pragma unroll
        for (int kk = 0; kk < KC; kk++) {
            float wr = sW[0][j][kk];
            float wz = sW[1][j][kk];
            float wn = sW[2][j][kk];
#pragma unroll
            for (int i = 0; i < 4; i++) {
                float hv = sH[bb + i][kk];
                accr[i] += wr * hv;
                accz[i] += wz * hv;
                accn[i] += wn * hv;
            }
        }
        __syncthreads();
    }

    // write partials
#pragma unroll
    for (int i = 0; i < 4; i++) {
        int b = bb + i;
        int c = j0 + j;
        size_t base = ((size_t)s * BATCH + b) * G3;
        g_PART[base + c]        = accr[i];
        g_PART[base + 512 + c]  = accz[i];
        g_PART[base + 1024 + c] = accn[i];
    }
    __threadfence();

    __shared__ unsigned int sLast;
    if (tid == 0) {
        unsigned int old = atomicAdd(&g_CNT[tile], 1u);
        sLast = ((old % SPLIT) == SPLIT - 1) ? 1u : 0u;
    }
    __syncthreads();
    if (!sLast) return;
    __threadfence();   // ensure other splits' partials are visible

    // combine: 64 batches x 16 columns, 4 outputs / thread, deterministic order
#pragma unroll
    for (int q = 0; q < 4; q++) {
        int idx = q * 256 + tid;     // 0..1023
        int jj  = idx & (JT - 1);
        int b   = idx / JT;
        int c   = j0 + jj;
        float gr = bhh[c], gz = bhh[512 + c], gn = bhh[1024 + c];
#pragma unroll
        for (int ss = 0; ss < SPLIT; ss++) {
            size_t base = ((size_t)ss * BATCH + b) * G3;
            gr += g_PART[base + c];
            gz += g_PART[base + 512 + c];
            gn += g_PART[base + 1024 + c];
        }
        size_t gib = ((size_t)b * T + t) * G3;
        float ir  = GI[gib + c];
        float iz  = GI[gib + 512 + c];
        float inn = GI[gib + 1024 + c];
        float r = 1.0f / (1.0f + expf(-(ir + gr)));
        float z = 1.0f / (1.0f + expf(-(iz + gz)));
        float n = tanhf(inn + r * gn);
        float hp = h_in[b * HID + c];
        float hv = (1.0f - z) * n + z * hp;
        h_out[b * HID + c] = hv;
        Yout[((size_t)b * T + t) * HID + c] = hv;
    }
}

// ---------------- launch -----------------------------------------------------
extern "C" void kernel_launch(void* const* d_in, const int* in_sizes, int n_in,
                              void* d_out, int out_size)
{
    const int*   src     = (const int*)  d_in[0];
    const int*   trg     = (const int*)  d_in[1];
    const float* enc_emb = (const float*)d_in[2];
    const float* enc_Wih = (const float*)d_in[3];
    const float* enc_Whh = (const float*)d_in[4];
    const float* enc_bih = (const float*)d_in[5];
    const float* enc_bhh = (const float*)d_in[6];
    const float* dec_emb = (const float*)d_in[7];
    const float* dec_Wih = (const float*)d_in[8];
    const float* dec_Whh = (const float*)d_in[9];
    const float* dec_bih = (const float*)d_in[10];
    const float* dec_bhh = (const float*)d_in[11];
    const float* fc_W    = (const float*)d_in[12];
    const float* fc_b    = (const float*)d_in[13];
    float* out = (float*)d_out;

    float *X, *GI, *Y, *H;
    cudaGetSymbolAddress((void**)&X,  g_X);
    cudaGetSymbolAddress((void**)&GI, g_GI);
    cudaGetSymbolAddress((void**)&Y,  g_Y);
    cudaGetSymbolAddress((void**)&H,  g_H);

    // zero t=0 output slice + initial hidden states
    init_k<<<(BATCH * VOCAB + 255) / 256, 256>>>(out);

    float* finals[2];

    // ===================== encoder =====================
    embed_k<<<(BATCH * TSRC * (EMB / 4) + 255) / 256, 256>>>(src, enc_emb, X, TSRC);
    for (int l = 0; l < 2; l++) {
        const float* Ain = (l == 0) ? X : Y;
        gemm_bias<<<dim3((BATCH * TSRC) / GTM, G3 / GTN), 256>>>(
            Ain, enc_Wih + (size_t)l * G3 * HID, enc_bih + l * G3,
            GI, BATCH * TSRC, G3, (l == 0) ? EMB : HID, 0);
        float* hc = H + (2 * l + 0) * BATCH * HID;
        float* hn = H + (2 * l + 1) * BATCH * HID;
        for (int t = 0; t < TSRC; t++) {
            gru_step<<<128, 256>>>(hc, enc_Whh + (size_t)l * G3 * HID,
                                   enc_bhh + l * G3, GI, t, TSRC, hn, Y);
            float* tmp = hc; hc = hn; hn = tmp;
        }
        finals[l] = hc;   // final hidden of this layer
    }

    // ===================== decoder =====================
    embed_k<<<(BATCH * TDEC * (EMB / 4) + 255) / 256, 256>>>(trg, dec_emb, X, TDEC);
    for (int l = 0; l < 2; l++) {
        const float* Ain = (l == 0) ? X : Y;
        gemm_bias<<<dim3((BATCH * TDEC) / GTM, G3 / GTN), 256>>>(
            Ain, dec_Wih + (size_t)l * G3 * HID, dec_bih + l * G3,
            GI, BATCH * TDEC, G3, (l == 0) ? EMB : HID, 0);
        float* hc = finals[l];
        float* p0 = H + (2 * l + 0) * BATCH * HID;
        float* p1 = H + (2 * l + 1) * BATCH * HID;
        float* hn = (hc == p0) ? p1 : p0;
        for (int t = 0; t < TDEC; t++) {
            gru_step<<<128, 256>>>(hc, dec_Whh + (size_t)l * G3 * HID,
                                   dec_bhh + l * G3, GI, t, TDEC, hn, Y);
            float* tmp = hc; hc = hn; hn = tmp;
        }
    }

    // ===================== FC head =====================
    gemm_bias<<<dim3((BATCH * TDEC) / GTM, (VOCAB + GTN - 1) / GTN), 256>>>(
        Y, fc_W, fc_b, out, BATCH * TDEC, VOCAB, HID, 1);
}

// round 6
// speedup vs baseline: 1.2571x; 1.2571x over previous
#include <cuda_runtime.h>
#include <math.h>

#define BATCH 64
#define EMB   512
#define HID   512
#define G3    1536         // 3*HID
#define VOCAB 10000
#define TSRC  128
#define TDEC  127          // trg[:, :-1]

// persistent GRU kernel geometry
#define NBLK  128          // blocks (<= SM count, all co-resident)
#define CPB   4            // h-columns per block (128*4 = 512)
#define KCH   64           // k-chunk staged per double-buffer slot
#define NKCH  (HID / KCH)  // 8
#define SW_ROW 516         // padded row (floats) for weight smem (bank-conflict-free float4)
#define SH_ROW 68          // padded row (floats) for h smem
#define SW_FLOATS (3 * CPB * SW_ROW)          // 6192
#define SH_FLOATS (2 * BATCH * SH_ROW)        // 8704
#define GRU_SMEM  ((SW_FLOATS + SH_FLOATS) * 4)  // 59584 bytes

// ---------------- scratch (device globals; no allocation allowed) ----------
__device__ float g_X [(size_t)BATCH * TSRC * EMB];   // embedded inputs
__device__ float g_GI[(size_t)BATCH * TSRC * G3];    // input projections (all t)
__device__ float g_Y [(size_t)BATCH * TSRC * HID];   // layer outputs
__device__ float g_H [4 * BATCH * HID];              // ping-pong hidden (2 layers x 2)
__device__ unsigned int g_GEN;                       // barrier generation (monotonic)
__device__ unsigned int g_BCNT;                      // barrier arrival count (returns to 0)

// ---------------- init: zero out[t=0] slice + hidden buffers ----------------
__global__ void init_k(float* __restrict__ out)
{
    int i = blockIdx.x * blockDim.x + threadIdx.x;
    if (i < BATCH * VOCAB) {
        int b = i / VOCAB, v = i % VOCAB;
        out[((size_t)b * TSRC) * VOCAB + v] = 0.0f;
    }
    if (i < 4 * BATCH * HID) g_H[i] = 0.0f;
}

// ---------------- embedding gather (float4) ---------------------------------
__global__ void embed_k(const int* __restrict__ idx, const float* __restrict__ emb,
                        float* __restrict__ X, int T)
{
    int i = blockIdx.x * blockDim.x + threadIdx.x;
    int total = BATCH * T * (EMB / 4);
    if (i >= total) return;
    int e4 = i % (EMB / 4);
    int bt = i / (EMB / 4);
    int t  = bt % T;
    int b  = bt / T;
    int tok = idx[b * TSRC + t];               // idx rows have stride TSRC (128)
    reinterpret_cast<float4*>(X)[(size_t)bt * (EMB / 4) + e4] =
        reinterpret_cast<const float4*>(emb)[(size_t)tok * (EMB / 4) + e4];
}

// ---------------- generic tiled GEMM: C = A[M,K] @ W[N,K]^T + bias ----------
// mode 0: C[m*N + n]
// mode 1: FC scatter: m -> (b = m/TDEC, t = m%TDEC), C[((b*TSRC)+t+1)*VOCAB + n]
#define GTM 64
#define GTN 64
#define GTK 16
__global__ __launch_bounds__(256) void gemm_bias(
    const float* __restrict__ A, const float* __restrict__ W,
    const float* __restrict__ bias, float* __restrict__ C,
    int M, int N, int K, int mode)
{
    __shared__ float sA[GTK][GTM];
    __shared__ float sB[GTK][GTN];
    int m0 = blockIdx.x * GTM;
    int n0 = blockIdx.y * GTN;
    int tid = threadIdx.x;
    int tx = tid & 15;          // n micro index
    int ty = tid >> 4;          // m micro index
    int lm = tid >> 2;          // 0..63 (row for staging)
    int lk = (tid & 3) * 4;     // 0,4,8,12

    float acc[4][4];
#pragma unroll
    for (int i = 0; i < 4; i++)
#pragma unroll
        for (int j = 0; j < 4; j++) acc[i][j] = 0.0f;

    for (int k0 = 0; k0 < K; k0 += GTK) {
        float4 av = *reinterpret_cast<const float4*>(&A[(size_t)(m0 + lm) * K + k0 + lk]);
        float4 bv = make_float4(0.f, 0.f, 0.f, 0.f);
        int wn = n0 + lm;
        if (wn < N)
            bv = *reinterpret_cast<const float4*>(&W[(size_t)wn * K + k0 + lk]);
        __syncthreads();
        sA[lk + 0][lm] = av.x; sA[lk + 1][lm] = av.y;
        sA[lk + 2][lm] = av.z; sA[lk + 3][lm] = av.w;
        sB[lk + 0][lm] = bv.x; sB[lk + 1][lm] = bv.y;
        sB[lk + 2][lm] = bv.z; sB[lk + 3][lm] = bv.w;
        __syncthreads();
#pragma unroll
        for (int k = 0; k < GTK; k++) {
            float a[4], b[4];
            *reinterpret_cast<float4*>(a) = *reinterpret_cast<const float4*>(&sA[k][ty * 4]);
            *reinterpret_cast<float4*>(b) = *reinterpret_cast<const float4*>(&sB[k][tx * 4]);
#pragma unroll
            for (int i = 0; i < 4; i++)
#pragma unroll
                for (int j = 0; j < 4; j++)
                    acc[i][j] += a[i] * b[j];
        }
    }

#pragma unroll
    for (int i = 0; i < 4; i++) {
        int m = m0 + ty * 4 + i;
        size_t rowbase;
        if (mode == 0) {
            rowbase = (size_t)m * N;
        } else {
            int b = m / TDEC, t = m % TDEC;
            rowbase = ((size_t)b * TSRC + t + 1) * VOCAB;
        }
#pragma unroll
        for (int j = 0; j < 4; j++) {
            int n = n0 + tx * 4 + j;
            if (n < N) {
                C[rowbase + n] = acc[i][j] + bias[n];
            }
        }
    }
}

// ---------------- helpers for persistent GRU --------------------------------
__device__ __forceinline__ void cp_async16(void* smem_dst, const void* gmem_src)
{
    unsigned int saddr = (unsigned int)__cvta_generic_to_shared(smem_dst);
    asm volatile("cp.async.cg.shared.global [%0], [%1], 16;\n"
                 :: "r"(saddr), "l"(gmem_src) : "memory");
}

__device__ __forceinline__ void grid_barrier()
{
    __threadfence();
    __syncthreads();
    if (threadIdx.x == 0) {
        volatile unsigned int* genp = &g_GEN;
        unsigned int my = *genp;
        unsigned int old = atomicAdd(&g_BCNT, 1u);
        if (old == NBLK - 1u) {
            atomicExch(&g_BCNT, 0u);
            __threadfence();
            atomicAdd(&g_GEN, 1u);
        } else {
            while (*genp == my) { __nanosleep(32); }
        }
    }
    __syncthreads();
}

// ---------------- persistent GRU layer: all T steps in one launch -----------
// Each block owns CPB=4 output columns; weights for its 12 Whh rows live in
// smem for the whole layer. Per step, h (128KB) is streamed through smem in
// 8 double-buffered cp.async.cg chunks (L1-bypassing: h is produced by other
// SMs within this same launch). One grid barrier per step.
__global__ __launch_bounds__(256, 1) void gru_layer(
    const float* __restrict__ Whh, const float* __restrict__ bhh,
    const float* __restrict__ GI, int T,
    float* __restrict__ hbuf0, float* __restrict__ hbuf1,
    float* __restrict__ Yout)
{
    extern __shared__ float smem[];
    float* sW = smem;                 // [3][CPB][SW_ROW]
    float* sH = smem + SW_FLOATS;     // [2][BATCH][SH_ROW]

    const int tid = threadIdx.x;
    const int bid = blockIdx.x;
    const int c0  = bid * CPB;
    const int c   = tid & 3;          // column within block
    const int b   = tid >> 2;         // batch 0..63
    const int cg  = c0 + c;           // global h column
    const int qh  = c0 >> 6;          // k-chunk containing column cg (for h_prev)

    // ---- load this block's Whh slice into smem (once per layer) ----
    for (int idx = tid; idx < 3 * CPB * (HID / 4); idx += 256) {
        int r  = idx >> 7;            // 0..11 (HID/4 = 128 float4 per row)
        int k4 = idx & 127;
        int g  = r >> 2;
        int cc = r & 3;
        float4 v = reinterpret_cast<const float4*>(Whh)
                      [(size_t)(g * HID + c0 + cc) * (HID / 4) + k4];
        *(reinterpret_cast<float4*>(sW + (g * CPB + cc) * SW_ROW) + k4) = v;
    }
    const float br = bhh[cg];
    const float bz = bhh[HID + cg];
    const float bn = bhh[2 * HID + cg];
    __syncthreads();

    const float4* w4r = reinterpret_cast<const float4*>(sW + (0 * CPB + c) * SW_ROW);
    const float4* w4z = reinterpret_cast<const float4*>(sW + (1 * CPB + c) * SW_ROW);
    const float4* w4n = reinterpret_cast<const float4*>(sW + (2 * CPB + c) * SW_ROW);

    for (int t = 0; t < T; t++) {
        const float* hin  = (t & 1) ? hbuf1 : hbuf0;
        float*       hout = (t & 1) ? hbuf0 : hbuf1;

        // stage chunk 0
        for (int i = tid; i < BATCH * (KCH / 4); i += 256) {
            int bb = i >> 4, k4 = i & 15;
            cp_async16(sH + bb * SH_ROW + k4 * 4, hin + bb * HID + k4 * 4);
        }
        asm volatile("cp.async.commit_group;\n" ::: "memory");

        float gr = 0.f, gz = 0.f, gn = 0.f;
        float hprev = 0.f;

        for (int q = 0; q < NKCH; q++) {
            if (q + 1 < NKCH) {
                float* dst = sH + ((q + 1) & 1) * BATCH * SH_ROW;
                const float* src = hin + (q + 1) * KCH;
                for (int i = tid; i < BATCH * (KCH / 4); i += 256) {
                    int bb = i >> 4, k4 = i & 15;
                    cp_async16(dst + bb * SH_ROW + k4 * 4, src + bb * HID + k4 * 4);
                }
                asm volatile("cp.async.commit_group;\n" ::: "memory");
                asm volatile("cp.async.wait_group 1;\n" ::: "memory");
            } else {
                asm volatile("cp.async.wait_group 0;\n" ::: "memory");
            }
            __syncthreads();

            const float4* h4 = reinterpret_cast<const float4*>(
                sH + (q & 1) * BATCH * SH_ROW + b * SH_ROW);
            const int kb4 = q * (KCH / 4);
#pragma unroll
            for (int k4 = 0; k4 < KCH / 4; k4++) {
                float4 hv = h4[k4];
                float4 wr = w4r[kb4 + k4];
                float4 wz = w4z[kb4 + k4];
                float4 wn = w4n[kb4 + k4];
                gr += wr.x * hv.x + wr.y * hv.y + wr.z * hv.z + wr.w * hv.w;
                gz += wz.x * hv.x + wz.y * hv.y + wz.z * hv.z + wz.w * hv.w;
                gn += wn.x * hv.x + wn.y * hv.y + wn.z * hv.z + wn.w * hv.w;
            }
            if (q == qh)
                hprev = sH[(q & 1) * BATCH * SH_ROW + b * SH_ROW + (cg & (KCH - 1))];
            __syncthreads();
        }

        // ---- fused gate epilogue (deterministic, per-thread) ----
        size_t gib = ((size_t)b * T + t) * G3;
        float ir  = GI[gib + cg];
        float iz  = GI[gib + HID + cg];
        float inn = GI[gib + 2 * HID + cg];
        float r = 1.0f / (1.0f + expf(-(ir + gr + br)));
        float z = 1.0f / (1.0f + expf(-(iz + gz + bz)));
        float n = tanhf(inn + r * (gn + bn));
        float hv = (1.0f - z) * n + z * hprev;
        hout[b * HID + cg] = hv;
        Yout[((size_t)b * T + t) * HID + cg] = hv;

        grid_barrier();
    }
}

// ---------------- launch -----------------------------------------------------
extern "C" void kernel_launch(void* const* d_in, const int* in_sizes, int n_in,
                              void* d_out, int out_size)
{
    const int*   src     = (const int*)  d_in[0];
    const int*   trg     = (const int*)  d_in[1];
    const float* enc_emb = (const float*)d_in[2];
    const float* enc_Wih = (const float*)d_in[3];
    const float* enc_Whh = (const float*)d_in[4];
    const float* enc_bih = (const float*)d_in[5];
    const float* enc_bhh = (const float*)d_in[6];
    const float* dec_emb = (const float*)d_in[7];
    const float* dec_Wih = (const float*)d_in[8];
    const float* dec_Whh = (const float*)d_in[9];
    const float* dec_bih = (const float*)d_in[10];
    const float* dec_bhh = (const float*)d_in[11];
    const float* fc_W    = (const float*)d_in[12];
    const float* fc_b    = (const float*)d_in[13];
    float* out = (float*)d_out;

    float *X, *GI, *Y, *H;
    cudaGetSymbolAddress((void**)&X,  g_X);
    cudaGetSymbolAddress((void**)&GI, g_GI);
    cudaGetSymbolAddress((void**)&Y,  g_Y);
    cudaGetSymbolAddress((void**)&H,  g_H);

    static int smem_set = 0;
    if (!smem_set) {
        cudaFuncSetAttribute(gru_layer, cudaFuncAttributeMaxDynamicSharedMemorySize,
                             GRU_SMEM);
        smem_set = 1;
    }

    // zero t=0 output slice + initial hidden states
    init_k<<<(BATCH * VOCAB + 255) / 256, 256>>>(out);

    // ===================== encoder =====================
    embed_k<<<(BATCH * TSRC * (EMB / 4) + 255) / 256, 256>>>(src, enc_emb, X, TSRC);
    for (int l = 0; l < 2; l++) {
        const float* Ain = (l == 0) ? X : Y;
        gemm_bias<<<dim3((BATCH * TSRC) / GTM, G3 / GTN), 256>>>(
            Ain, enc_Wih + (size_t)l * G3 * HID, enc_bih + l * G3,
            GI, BATCH * TSRC, G3, (l == 0) ? EMB : HID, 0);
        float* h0 = H + (2 * l + 0) * BATCH * HID;
        float* h1 = H + (2 * l + 1) * BATCH * HID;
        // T=128 (even): final hidden ends in h0 — exactly where decoder reads it.
        gru_layer<<<NBLK, 256, GRU_SMEM>>>(
            enc_Whh + (size_t)l * G3 * HID, enc_bhh + l * G3, GI, TSRC, h0, h1, Y);
    }

    // ===================== decoder =====================
    embed_k<<<(BATCH * TDEC * (EMB / 4) + 255) / 256, 256>>>(trg, dec_emb, X, TDEC);
    for (int l = 0; l < 2; l++) {
        const float* Ain = (l == 0) ? X : Y;
        gemm_bias<<<dim3((BATCH * TDEC) / GTM, G3 / GTN), 256>>>(
            Ain, dec_Wih + (size_t)l * G3 * HID, dec_bih + l * G3,
            GI, BATCH * TDEC, G3, (l == 0) ? EMB : HID, 0);
        float* h0 = H + (2 * l + 0) * BATCH * HID;   // holds encoder final hidden
        float* h1 = H + (2 * l + 1) * BATCH * HID;
        gru_layer<<<NBLK, 256, GRU_SMEM>>>(
            dec_Whh + (size_t)l * G3 * HID, dec_bhh + l * G3, GI, TDEC, h0, h1, Y);
    }

    // ===================== FC head =====================
    gemm_bias<<<dim3((BATCH * TDEC) / GTM, (VOCAB + GTN - 1) / GTN), 256>>>(
        Y, fc_W, fc_b, out, BATCH * TDEC, VOCAB, HID, 1);
}